// round 14
// baseline (speedup 1.0000x reference)
#include <cuda_runtime.h>
#include <cuda_fp16.h>
#include <cstdint>
#include <math.h>

#define SEQ 2048
#define EMB 1024
#define NH  16
#define HD  64
#define BATCH 2
#define MTOT (BATCH*SEQ)   // 4096

// ---------------------------------------------------------------------------
// Scratch (__device__ globals: allocation-free rule)
// ---------------------------------------------------------------------------
__device__ __half g_X[MTOT*EMB];
__device__ __half g_W[4][EMB*EMB];     // Wq, Wk, Wv contiguous; Wu last
__device__ __half g_Q[MTOT*EMB];
__device__ __half g_K[MTOT*EMB];
__device__ __half g_V[MTOT*EMB];
__device__ __half g_C[MTOT*EMB];

// ---------------------------------------------------------------------------
// PTX helpers (arch-portable; tcgen05 unusable: harness compiles compute_103)
// ---------------------------------------------------------------------------
__device__ __forceinline__ uint32_t smem_u32(const void* p) {
    uint32_t a;
    asm("{ .reg .u64 t; cvta.to.shared.u64 t, %1; cvt.u32.u64 %0, t; }"
        : "=r"(a) : "l"(p));
    return a;
}

#define CP_ASYNC16(dst, src) \
    asm volatile("cp.async.cg.shared.global [%0], [%1], 16;" :: "r"(dst), "l"(src))
#define CP_COMMIT() asm volatile("cp.async.commit_group;" ::: "memory")
#define CP_WAIT0()  asm volatile("cp.async.wait_group 0;" ::: "memory")
#define CP_WAIT1()  asm volatile("cp.async.wait_group 1;" ::: "memory")

#define LDMATRIX_X4(r0, r1, r2, r3, addr) \
    asm volatile("ldmatrix.sync.aligned.m8n8.x4.shared.b16 {%0,%1,%2,%3}, [%4];" \
        : "=r"(r0), "=r"(r1), "=r"(r2), "=r"(r3) : "r"(addr))
#define LDMATRIX_X4_T(r0, r1, r2, r3, addr) \
    asm volatile("ldmatrix.sync.aligned.m8n8.x4.trans.shared.b16 {%0,%1,%2,%3}, [%4];" \
        : "=r"(r0), "=r"(r1), "=r"(r2), "=r"(r3) : "r"(addr))

#define MMA_F16(c0, c1, c2, c3, a0, a1, a2, a3, b0, b1) \
    asm volatile("mma.sync.aligned.m16n8k16.row.col.f32.f16.f16.f32 " \
        "{%0,%1,%2,%3}, {%4,%5,%6,%7}, {%8,%9}, {%0,%1,%2,%3};" \
        : "+f"(c0), "+f"(c1), "+f"(c2), "+f"(c3) \
        : "r"(a0), "r"(a1), "r"(a2), "r"(a3), "r"(b0), "r"(b1))

// packed fp16x2 exp2 (PTX ISA 7.0+, arch-portable)
#define EX2_H2(r) asm("ex2.approx.f16x2 %0, %0;" : "+r"(r))

#define HONES 0x3C003C00u   // half2(1.0, 1.0)

__device__ __forceinline__ uint32_t pack_h2(float x, float y) {
    __half2 t = __floats2half2_rn(x, y);
    return *reinterpret_cast<uint32_t*>(&t);
}

// ---------------------------------------------------------------------------
// Preprocessing: y=0..3 -> W matrix y -> fp16; y=4..7 -> x quarter -> fp16.
// ---------------------------------------------------------------------------
__global__ void prep_kernel(const float* __restrict__ x,
                            const float* __restrict__ w0, const float* __restrict__ w1,
                            const float* __restrict__ w2, const float* __restrict__ w3,
                            __half* __restrict__ W, __half* __restrict__ X)
{
    const int m = blockIdx.y;
    const int n4 = (EMB * EMB) / 4;
    int i = blockIdx.x * blockDim.x + threadIdx.x;
    int stride = gridDim.x * blockDim.x;
    const float4* in;
    __half2* op;
    if (m < 4) {
        in = (const float4*)((m == 0) ? w0 : (m == 1) ? w1 : (m == 2) ? w2 : w3);
        op = (__half2*)(W + (size_t)m * EMB * EMB);
    } else {
        const size_t off = (size_t)(m - 4) * EMB * EMB;
        in = (const float4*)(x + off);
        op = (__half2*)(X + off);
    }
    for (; i < n4; i += stride) {
        float4 v = in[i];
        op[2*i + 0] = __floats2half2_rn(v.x, v.y);
        op[2*i + 1] = __floats2half2_rn(v.z, v.w);
    }
}

// ---------------------------------------------------------------------------
// fp16 single-pass HMMA GEMM: Y = A B^T.
// CTA tile 128(m) x 256(n), 256 threads = 8 warps (2x4), warp tile 64x64.
// 1 CTA/SM (8 warps/SM, same as before) but HALF the L2 B-traffic.
// BK=32, 3-stage cp.async.
// MODE 0: fp32 out + bias. MODE 1: QKV fused fp16 outputs (Q scaled).
// ---------------------------------------------------------------------------
#define ROWB      80
#define ATILE_B   (128 * ROWB)            // 10240
#define BTILE_B   (256 * ROWB)            // 20480
#define STAGE_B   (ATILE_B + BTILE_B)     // 30720
#define T_B       ATILE_B
#define GEMM_SMEM (3 * STAGE_B)           // 92160

template<int MODE>
__global__ __launch_bounds__(256, 1)
void gemm_hmma(const __half* __restrict__ A, const __half* __restrict__ B,
               float* __restrict__ Y, const float* __restrict__ bias,
               __half* __restrict__ Qp, __half* __restrict__ Kp, __half* __restrict__ Vp,
               float qscale, int K)
{
    extern __shared__ char sm[];
    const uint32_t smb = smem_u32(sm);

    const int tid  = threadIdx.x;
    const int lane = tid & 31;
    const int wid  = tid >> 5;
    const int wm   = wid >> 2;                // 0..1
    const int wn   = wid & 3;                 // 0..3
    const int rowBase = blockIdx.y * 128;
    const int colBase = blockIdx.x * 256;

    auto load_chunk = [&](int c, int st) {
        const uint32_t sb = smb + st * STAGE_B;
        // A: 128 rows x 4 segs = 512 segs -> 2 iters
#pragma unroll
        for (int it = 0; it < 2; it++) {
            int idx = tid + it * 256;
            int row = idx >> 2, seg = idx & 3;
            const __half* src = A + (size_t)(rowBase + row) * K + c * 32 + seg * 8;
            CP_ASYNC16(sb + (uint32_t)row * ROWB + seg * 16, src);
        }
        // B: 256 rows x 4 segs = 1024 segs -> 4 iters
#pragma unroll
        for (int it = 0; it < 4; it++) {
            int idx = tid + it * 256;
            int row = idx >> 2, seg = idx & 3;
            const __half* src = B + (size_t)(colBase + row) * K + c * 32 + seg * 8;
            CP_ASYNC16(sb + T_B + (uint32_t)row * ROWB + seg * 16, src);
        }
        CP_COMMIT();
    };

    const int aRow = (lane & 7) + ((lane >> 3) & 1) * 8;
    const int aK   = (lane >> 4) * 8;
    const uint32_t aBase = (uint32_t)(wm * 64 + aRow) * ROWB + aK * 2;
    const int bRow4 = (lane & 7) + ((lane >> 4) & 1) * 8;
    const int bK4   = ((lane >> 3) & 1) * 8;
    const uint32_t bBase = (uint32_t)(wn * 64 + bRow4) * ROWB + bK4 * 2;

    float acc[4][8][4];
#pragma unroll
    for (int i = 0; i < 4; i++)
#pragma unroll
        for (int j = 0; j < 8; j++)
#pragma unroll
            for (int r = 0; r < 4; r++) acc[i][j][r] = 0.f;

    const int NC = K / 32;

    load_chunk(0, 0);
    load_chunk(1, 1);

    for (int c = 0; c < NC; c++) {
        CP_WAIT1();
        __syncthreads();
        if (c + 2 < NC) load_chunk(c + 2, (c + 2) % 3);

        const uint32_t sb = smb + (c % 3) * STAGE_B;

#pragma unroll
        for (int ks = 0; ks < 2; ks++) {
            const uint32_t kOff = ks * 32;

            uint32_t af[4][4], bf[8][2];
#pragma unroll
            for (int i = 0; i < 4; i++) {
                const uint32_t ao = aBase + (uint32_t)i * 16 * ROWB + kOff;
                LDMATRIX_X4(af[i][0], af[i][1], af[i][2], af[i][3], sb + ao);
            }
#pragma unroll
            for (int j8 = 0; j8 < 4; j8++) {
                const uint32_t bo = bBase + (uint32_t)j8 * 16 * ROWB + kOff;
                LDMATRIX_X4(bf[2*j8][0], bf[2*j8][1], bf[2*j8+1][0], bf[2*j8+1][1],
                            sb + T_B + bo);
            }

#pragma unroll
            for (int i = 0; i < 4; i++)
#pragma unroll
                for (int j = 0; j < 8; j++)
                    MMA_F16(acc[i][j][0], acc[i][j][1], acc[i][j][2], acc[i][j][3],
                            af[i][0], af[i][1], af[i][2], af[i][3],
                            bf[j][0], bf[j][1]);
        }
        __syncthreads();
    }

    if (MODE == 0) {
#pragma unroll
        for (int i = 0; i < 4; i++) {
            const int r0 = rowBase + wm * 64 + i * 16 + (lane >> 2);
#pragma unroll
            for (int j = 0; j < 8; j++) {
                const int c0 = colBase + wn * 64 + j * 8 + (lane & 3) * 2;
                float bx = bias[c0], by = bias[c0 + 1];
                float2 v0 = { acc[i][j][0] + bx, acc[i][j][1] + by };
                float2 v1 = { acc[i][j][2] + bx, acc[i][j][3] + by };
                *(float2*)&Y[(size_t)r0 * EMB + c0]       = v0;
                *(float2*)&Y[(size_t)(r0 + 8) * EMB + c0] = v1;
            }
        }
    } else {
        const int mat = blockIdx.x >> 2;       // 0=Q, 1=K, 2=V
        __half* dst = (mat == 0) ? Qp : (mat == 1) ? Kp : Vp;
        const float scale = (mat == 0) ? qscale : 1.0f;
        const int colLoc = (colBase & 1023);
#pragma unroll
        for (int i = 0; i < 4; i++) {
            const int r0 = rowBase + wm * 64 + i * 16 + (lane >> 2);
#pragma unroll
            for (int j = 0; j < 8; j++) {
                const int c0 = colLoc + wn * 64 + j * 8 + (lane & 3) * 2;
#pragma unroll
                for (int rr = 0; rr < 2; rr++) {
                    __half2 v = __floats2half2_rn(acc[i][j][rr*2 + 0] * scale,
                                                  acc[i][j][rr*2 + 1] * scale);
                    *reinterpret_cast<__half2*>(&dst[(size_t)(r0 + rr*8) * EMB + c0]) = v;
                }
            }
        }
    }
}

// ---------------------------------------------------------------------------
// fp16 tensor-core causal flash attention (unchanged from round 13).
// P = exp2(s) raw via ex2.approx.f16x2; l via tensor-core ones-MMA.
// CTA: 64 q rows, 128 threads (4 warps). Bc=64 tiles, double-buffered KV.
// Diagonal tile peeled with per-warp causal culling.
// ---------------------------------------------------------------------------
#define AROWB   144
#define QT      (64 * AROWB)             // 9216
#define KVT     (64 * AROWB)             // 9216
#define KVST    (2 * KVT)
#define ATTN_SMEM (QT + 2*KVST)          // 46080

__global__ __launch_bounds__(128, 4)
void attn_mma(const __half* __restrict__ Qg,
              const __half* __restrict__ Kg, const __half* __restrict__ Vg,
              __half* __restrict__ C)
{
    extern __shared__ char sm[];
    const uint32_t smb = smem_u32(sm);
    const int tid  = threadIdx.x;
    const int lane = tid & 31;
    const int wid  = tid >> 5;
    const int qb = gridDim.x - 1 - blockIdx.x;      // heavy CTAs first
    const int h = blockIdx.y, b = blockIdx.z;
    const size_t tok0 = (size_t)b * SEQ;
    const int col0  = h * HD;
    const int qrow0 = qb * 64;

#pragma unroll
    for (int i = 0; i < 4; i++) {
        int idx = tid + i * 128;
        int row = idx >> 3, seg = idx & 7;
        const __half* src = Qg + (tok0 + qrow0 + row) * EMB + col0 + seg * 8;
        CP_ASYNC16(smb + (uint32_t)row * AROWB + seg * 16, src);
    }
    CP_COMMIT();

    auto load_kv = [&](int t) {
        const int st = t & 1;
        const int kt = t * 64;
        const uint32_t sb = smb + QT + st * KVST;
#pragma unroll
        for (int i = 0; i < 8; i++) {
            int idx  = tid + i * 128;
            int arr  = idx >> 9;
            int idx2 = idx & 511;
            int row  = idx2 >> 3, seg = idx2 & 7;
            const __half* src =
                (arr ? Vg : Kg) + (tok0 + kt + row) * EMB + col0 + seg * 8;
            CP_ASYNC16(sb + arr * KVT + (uint32_t)row * AROWB + seg * 16, src);
        }
        CP_COMMIT();
    };
    load_kv(0);

    const int aRow = (lane & 7) + ((lane >> 3) & 1) * 8;
    const int aK   = (lane >> 4) * 8;
    const int kRow = (lane & 7) + (lane >> 4) * 8;
    const int kC   = ((lane >> 3) & 1) * 8;

    uint32_t qf[4][4];
    CP_WAIT1();
    __syncthreads();
#pragma unroll
    for (int k16 = 0; k16 < 4; k16++) {
        const uint32_t qoff = (uint32_t)(wid*16 + aRow) * AROWB + (k16*16 + aK) * 2;
        LDMATRIX_X4(qf[k16][0], qf[k16][1], qf[k16][2], qf[k16][3], smb + qoff);
    }

    float cl[4];
#pragma unroll
    for (int r = 0; r < 4; r++) cl[r] = 0.f;
    float ctx[8][4];
#pragma unroll
    for (int j = 0; j < 8; j++)
#pragma unroll
        for (int r = 0; r < 4; r++) ctx[j][r] = 0.f;

    const int ntiles = qb + 1;

    // ---- main loop: full tiles, no causal mask ----
    for (int t = 0; t < ntiles - 1; t++) {
        load_kv(t + 1);
        CP_WAIT1();
        __syncthreads();

        const uint32_t sb = smb + QT + (t & 1) * KVST;

        float s[8][4];
#pragma unroll
        for (int j = 0; j < 8; j++)
#pragma unroll
            for (int r = 0; r < 4; r++) s[j][r] = 0.f;

#pragma unroll
        for (int k16 = 0; k16 < 4; k16++) {
            uint32_t kf[4][4];
#pragma unroll
            for (int pr = 0; pr < 4; pr++) {
                const uint32_t koff = (uint32_t)(pr*16 + kRow) * AROWB + (k16*16 + kC) * 2;
                LDMATRIX_X4(kf[pr][0], kf[pr][1], kf[pr][2], kf[pr][3], sb + koff);
            }
#pragma unroll
            for (int j = 0; j < 8; j++) {
                const uint32_t b0 = kf[j>>1][(j&1)*2], b1 = kf[j>>1][(j&1)*2 + 1];
                MMA_F16(s[j][0], s[j][1], s[j][2], s[j][3],
                        qf[k16][0], qf[k16][1], qf[k16][2], qf[k16][3], b0, b1);
            }
        }

#pragma unroll
        for (int k16 = 0; k16 < 4; k16++) {
            uint32_t aH[4];
#pragma unroll
            for (int g = 0; g < 2; g++) {
                const int j = 2*k16 + g;
                uint32_t p01 = pack_h2(s[j][0], s[j][1]);
                uint32_t p23 = pack_h2(s[j][2], s[j][3]);
                EX2_H2(p01);
                EX2_H2(p23);
                aH[2*g + 0] = p01;
                aH[2*g + 1] = p23;
            }

            uint32_t vf[4][4];
#pragma unroll
            for (int dp = 0; dp < 4; dp++) {
                const uint32_t voff = (uint32_t)(k16*16 + aRow) * AROWB + (dp*16 + aK) * 2;
                LDMATRIX_X4_T(vf[dp][0], vf[dp][1], vf[dp][2], vf[dp][3],
                              sb + KVT + voff);
            }
#pragma unroll
            for (int j = 0; j < 8; j++) {
                const uint32_t b0 = vf[j>>1][(j&1)*2], b1 = vf[j>>1][(j&1)*2 + 1];
                MMA_F16(ctx[j][0], ctx[j][1], ctx[j][2], ctx[j][3],
                        aH[0], aH[1], aH[2], aH[3], b0, b1);
            }
            MMA_F16(cl[0], cl[1], cl[2], cl[3],
                    aH[0], aH[1], aH[2], aH[3], HONES, HONES);
        }
        __syncthreads();
    }

    // ---- peeled diagonal tile: per-warp causal culling ----
    {
        CP_WAIT0();
        __syncthreads();

        const uint32_t sb = smb + QT + ((ntiles - 1) & 1) * KVST;
        const int kt = (ntiles - 1) * 64;
        const int r0g = qrow0 + wid*16 + (lane >> 2);
        const int jmax = 2*wid + 2;

        float s[8][4];
#pragma unroll
        for (int j = 0; j < 8; j++)
#pragma unroll
            for (int r = 0; r < 4; r++) s[j][r] = 0.f;

#pragma unroll
        for (int k16 = 0; k16 < 4; k16++) {
            uint32_t kf[4][4];
#pragma unroll
            for (int pr = 0; pr < 4; pr++) {
                if (pr <= wid) {
                    const uint32_t koff = (uint32_t)(pr*16 + kRow) * AROWB + (k16*16 + kC) * 2;
                    LDMATRIX_X4(kf[pr][0], kf[pr][1], kf[pr][2], kf[pr][3], sb + koff);
                }
            }
#pragma unroll
            for (int j = 0; j < 8; j++) {
                if (j < jmax) {
                    const uint32_t b0 = kf[j>>1][(j&1)*2], b1 = kf[j>>1][(j&1)*2 + 1];
                    MMA_F16(s[j][0], s[j][1], s[j][2], s[j][3],
                            qf[k16][0], qf[k16][1], qf[k16][2], qf[k16][3], b0, b1);
                }
            }
        }

#pragma unroll
        for (int j = 0; j < 8; j++) {
            if (j < jmax) {
                const int c = kt + j*8 + (lane & 3)*2;
                if (c     > r0g)     s[j][0] = -1e30f;
                if (c + 1 > r0g)     s[j][1] = -1e30f;
                if (c     > r0g + 8) s[j][2] = -1e30f;
                if (c + 1 > r0g + 8) s[j][3] = -1e30f;
            }
        }

#pragma unroll
        for (int k16 = 0; k16 < 4; k16++) {
            if (k16 <= wid) {
                uint32_t aH[4];
#pragma unroll
                for (int g = 0; g < 2; g++) {
                    const int j = 2*k16 + g;
                    uint32_t p01 = pack_h2(s[j][0], s[j][1]);
                    uint32_t p23 = pack_h2(s[j][2], s[j][3]);
                    EX2_H2(p01);
                    EX2_H2(p23);
                    aH[2*g + 0] = p01;
                    aH[2*g + 1] = p23;
                }

                uint32_t vf[4][4];
#pragma unroll
                for (int dp = 0; dp < 4; dp++) {
                    const uint32_t voff = (uint32_t)(k16*16 + aRow) * AROWB + (dp*16 + aK) * 2;
                    LDMATRIX_X4_T(vf[dp][0], vf[dp][1], vf[dp][2], vf[dp][3],
                                  sb + KVT + voff);
                }
#pragma unroll
                for (int j = 0; j < 8; j++) {
                    const uint32_t b0 = vf[j>>1][(j&1)*2], b1 = vf[j>>1][(j&1)*2 + 1];
                    MMA_F16(ctx[j][0], ctx[j][1], ctx[j][2], ctx[j][3],
                            aH[0], aH[1], aH[2], aH[3], b0, b1);
                }
                MMA_F16(cl[0], cl[1], cl[2], cl[3],
                        aH[0], aH[1], aH[2], aH[3], HONES, HONES);
            }
        }
    }

    const float inv0 = 1.f / cl[0], inv1 = 1.f / cl[2];

    const size_t rt0 = tok0 + qrow0 + wid*16 + (lane >> 2);
#pragma unroll
    for (int j = 0; j < 8; j++) {
        const int c = col0 + j*8 + (lane & 3)*2;
#pragma unroll
        for (int rr = 0; rr < 2; rr++) {
            __half2 v = __floats2half2_rn(ctx[j][rr*2 + 0] * (rr ? inv1 : inv0),
                                          ctx[j][rr*2 + 1] * (rr ? inv1 : inv0));
            *reinterpret_cast<__half2*>(&C[(rt0 + rr*8) * EMB + c]) = v;
        }
    }
}

// ---------------------------------------------------------------------------

extern "C" void kernel_launch(void* const* d_in, const int* in_sizes, int n_in,
                              void* d_out, int out_size)
{
    const float* x  = (const float*)d_in[0];
    const float* Wk = (const float*)d_in[1];
    const float* Wq = (const float*)d_in[2];
    const float* Wv = (const float*)d_in[3];
    const float* Wu = (const float*)d_in[4];
    const float* bu = (const float*)d_in[5];
    float* out = (float*)d_out;

    __half *Xp, *W, *Qp, *Kp, *Vp, *Cp;
    cudaGetSymbolAddress((void**)&Xp, g_X);
    cudaGetSymbolAddress((void**)&W,  g_W);
    cudaGetSymbolAddress((void**)&Qp, g_Q);
    cudaGetSymbolAddress((void**)&Kp, g_K);
    cudaGetSymbolAddress((void**)&Vp, g_V);
    cudaGetSymbolAddress((void**)&Cp, g_C);

    cudaFuncSetAttribute((const void*)gemm_hmma<0>,
                         cudaFuncAttributeMaxDynamicSharedMemorySize, GEMM_SMEM);
    cudaFuncSetAttribute((const void*)gemm_hmma<1>,
                         cudaFuncAttributeMaxDynamicSharedMemorySize, GEMM_SMEM);
    cudaFuncSetAttribute((const void*)attn_mma,
                         cudaFuncAttributeMaxDynamicSharedMemorySize, ATTN_SMEM);

    const float QSCALE = 0.125f * 1.44269504088896340736f;

    {
        dim3 pgrid(512, 8);
        prep_kernel<<<pgrid, 256>>>(x, Wq, Wk, Wv, Wu, W, Xp);
    }

    // fused Q/K/V projection: B rows 0..3071 = (Wq|Wk|Wv)
    {
        dim3 g(12, 32);                       // 384 CTAs, 128x256 tiles
        gemm_hmma<1><<<g, 256, GEMM_SMEM>>>(Xp, W, nullptr, nullptr,
                                            Qp, Kp, Vp, QSCALE, EMB);
    }

    {
        dim3 agrid(SEQ / 64, NH, BATCH);      // 1024 CTAs
        attn_mma<<<agrid, 128, ATTN_SMEM>>>(Qp, Kp, Vp, Cp);
    }

    {
        dim3 g(4, 32);                        // 128 CTAs, 128x256 tiles
        gemm_hmma<0><<<g, 256, GEMM_SMEM>>>(Cp, W + 3ll*EMB*EMB, out, bu,
                                            nullptr, nullptr, nullptr, 1.0f, EMB);
    }
}

// round 15
// speedup vs baseline: 1.1047x; 1.1047x over previous
#include <cuda_runtime.h>
#include <cuda_fp16.h>
#include <cstdint>
#include <math.h>

#define SEQ 2048
#define EMB 1024
#define NH  16
#define HD  64
#define BATCH 2
#define MTOT (BATCH*SEQ)   // 4096

// ---------------------------------------------------------------------------
// Scratch (__device__ globals: allocation-free rule)
// ---------------------------------------------------------------------------
__device__ __half g_X[MTOT*EMB];
__device__ __half g_W[4][EMB*EMB];     // Wq, Wk, Wv contiguous; Wu last
__device__ __half g_Q[MTOT*EMB];
__device__ __half g_K[MTOT*EMB];
__device__ __half g_V[MTOT*EMB];
__device__ __half g_C[MTOT*EMB];

// ---------------------------------------------------------------------------
// PTX helpers (arch-portable; tcgen05 unusable: harness compiles compute_103)
// ---------------------------------------------------------------------------
__device__ __forceinline__ uint32_t smem_u32(const void* p) {
    uint32_t a;
    asm("{ .reg .u64 t; cvta.to.shared.u64 t, %1; cvt.u32.u64 %0, t; }"
        : "=r"(a) : "l"(p));
    return a;
}

#define CP_ASYNC16(dst, src) \
    asm volatile("cp.async.cg.shared.global [%0], [%1], 16;" :: "r"(dst), "l"(src))
#define CP_COMMIT() asm volatile("cp.async.commit_group;" ::: "memory")
#define CP_WAIT0()  asm volatile("cp.async.wait_group 0;" ::: "memory")
#define CP_WAIT1()  asm volatile("cp.async.wait_group 1;" ::: "memory")

#define LDMATRIX_X4(r0, r1, r2, r3, addr) \
    asm volatile("ldmatrix.sync.aligned.m8n8.x4.shared.b16 {%0,%1,%2,%3}, [%4];" \
        : "=r"(r0), "=r"(r1), "=r"(r2), "=r"(r3) : "r"(addr))
#define LDMATRIX_X4_T(r0, r1, r2, r3, addr) \
    asm volatile("ldmatrix.sync.aligned.m8n8.x4.trans.shared.b16 {%0,%1,%2,%3}, [%4];" \
        : "=r"(r0), "=r"(r1), "=r"(r2), "=r"(r3) : "r"(addr))

#define MMA_F16(c0, c1, c2, c3, a0, a1, a2, a3, b0, b1) \
    asm volatile("mma.sync.aligned.m16n8k16.row.col.f32.f16.f16.f32 " \
        "{%0,%1,%2,%3}, {%4,%5,%6,%7}, {%8,%9}, {%0,%1,%2,%3};" \
        : "+f"(c0), "+f"(c1), "+f"(c2), "+f"(c3) \
        : "r"(a0), "r"(a1), "r"(a2), "r"(a3), "r"(b0), "r"(b1))

// packed fp16x2 exp2 (PTX ISA 7.0+, arch-portable)
#define EX2_H2(r) asm("ex2.approx.f16x2 %0, %0;" : "+r"(r))

#define HONES 0x3C003C00u   // half2(1.0, 1.0)

__device__ __forceinline__ uint32_t pack_h2(float x, float y) {
    __half2 t = __floats2half2_rn(x, y);
    return *reinterpret_cast<uint32_t*>(&t);
}

// ---------------------------------------------------------------------------
// Preprocessing: y=0..3 -> W matrix y -> fp16; y=4..7 -> x quarter -> fp16.
// ---------------------------------------------------------------------------
__global__ void prep_kernel(const float* __restrict__ x,
                            const float* __restrict__ w0, const float* __restrict__ w1,
                            const float* __restrict__ w2, const float* __restrict__ w3,
                            __half* __restrict__ W, __half* __restrict__ X)
{
    const int m = blockIdx.y;
    const int n4 = (EMB * EMB) / 4;
    int i = blockIdx.x * blockDim.x + threadIdx.x;
    int stride = gridDim.x * blockDim.x;
    const float4* in;
    __half2* op;
    if (m < 4) {
        in = (const float4*)((m == 0) ? w0 : (m == 1) ? w1 : (m == 2) ? w2 : w3);
        op = (__half2*)(W + (size_t)m * EMB * EMB);
    } else {
        const size_t off = (size_t)(m - 4) * EMB * EMB;
        in = (const float4*)(x + off);
        op = (__half2*)(X + off);
    }
    for (; i < n4; i += stride) {
        float4 v = in[i];
        op[2*i + 0] = __floats2half2_rn(v.x, v.y);
        op[2*i + 1] = __floats2half2_rn(v.z, v.w);
    }
}

// ---------------------------------------------------------------------------
// fp16 single-pass HMMA GEMM: Y = A B^T.
// CTA tile 128(m) x 256(n), 256 threads = 8 warps (2x4), warp tile 64x64.
// BK=64 (16 K-iterations: HALF the sync/wait events), 3-stage cp.async.
// MODE 0: fp32 out + bias. MODE 1: QKV fused fp16 outputs (Q scaled).
// ---------------------------------------------------------------------------
#define ROWB      144                     // 64 half = 128B data + 16B pad
#define ATILE_B   (128 * ROWB)            // 18432
#define BTILE_B   (256 * ROWB)            // 36864
#define STAGE_B   (ATILE_B + BTILE_B)     // 55296
#define T_B       ATILE_B
#define GEMM_SMEM (3 * STAGE_B)           // 165888

template<int MODE>
__global__ __launch_bounds__(256, 1)
void gemm_hmma(const __half* __restrict__ A, const __half* __restrict__ B,
               float* __restrict__ Y, const float* __restrict__ bias,
               __half* __restrict__ Qp, __half* __restrict__ Kp, __half* __restrict__ Vp,
               float qscale, int K)
{
    extern __shared__ char sm[];
    const uint32_t smb = smem_u32(sm);

    const int tid  = threadIdx.x;
    const int lane = tid & 31;
    const int wid  = tid >> 5;
    const int wm   = wid >> 2;                // 0..1
    const int wn   = wid & 3;                 // 0..3
    const int rowBase = blockIdx.y * 128;
    const int colBase = blockIdx.x * 256;

    auto load_chunk = [&](int c, int st) {
        const uint32_t sb = smb + st * STAGE_B;
        // A: 128 rows x 8 segs = 1024 segs -> 4 iters
#pragma unroll
        for (int it = 0; it < 4; it++) {
            int idx = tid + it * 256;
            int row = idx >> 3, seg = idx & 7;
            const __half* src = A + (size_t)(rowBase + row) * K + c * 64 + seg * 8;
            CP_ASYNC16(sb + (uint32_t)row * ROWB + seg * 16, src);
        }
        // B: 256 rows x 8 segs = 2048 segs -> 8 iters
#pragma unroll
        for (int it = 0; it < 8; it++) {
            int idx = tid + it * 256;
            int row = idx >> 3, seg = idx & 7;
            const __half* src = B + (size_t)(colBase + row) * K + c * 64 + seg * 8;
            CP_ASYNC16(sb + T_B + (uint32_t)row * ROWB + seg * 16, src);
        }
        CP_COMMIT();
    };

    const int aRow = (lane & 7) + ((lane >> 3) & 1) * 8;
    const int aK   = (lane >> 4) * 8;
    const uint32_t aBase = (uint32_t)(wm * 64 + aRow) * ROWB + aK * 2;
    const int bRow4 = (lane & 7) + ((lane >> 4) & 1) * 8;
    const int bK4   = ((lane >> 3) & 1) * 8;
    const uint32_t bBase = (uint32_t)(wn * 64 + bRow4) * ROWB + bK4 * 2;

    float acc[4][8][4];
#pragma unroll
    for (int i = 0; i < 4; i++)
#pragma unroll
        for (int j = 0; j < 8; j++)
#pragma unroll
            for (int r = 0; r < 4; r++) acc[i][j][r] = 0.f;

    const int NC = K / 64;    // 16

    load_chunk(0, 0);
    load_chunk(1, 1);

    for (int c = 0; c < NC; c++) {
        CP_WAIT1();
        __syncthreads();
        if (c + 2 < NC) load_chunk(c + 2, (c + 2) % 3);

        const uint32_t sb = smb + (c % 3) * STAGE_B;

#pragma unroll
        for (int ks = 0; ks < 4; ks++) {
            const uint32_t kOff = ks * 32;    // 16 half = 32B per k-step

            uint32_t af[4][4], bf[8][2];
#pragma unroll
            for (int i = 0; i < 4; i++) {
                const uint32_t ao = aBase + (uint32_t)i * 16 * ROWB + kOff;
                LDMATRIX_X4(af[i][0], af[i][1], af[i][2], af[i][3], sb + ao);
            }
#pragma unroll
            for (int j8 = 0; j8 < 4; j8++) {
                const uint32_t bo = bBase + (uint32_t)j8 * 16 * ROWB + kOff;
                LDMATRIX_X4(bf[2*j8][0], bf[2*j8][1], bf[2*j8+1][0], bf[2*j8+1][1],
                            sb + T_B + bo);
            }

#pragma unroll
            for (int i = 0; i < 4; i++)
#pragma unroll
                for (int j = 0; j < 8; j++)
                    MMA_F16(acc[i][j][0], acc[i][j][1], acc[i][j][2], acc[i][j][3],
                            af[i][0], af[i][1], af[i][2], af[i][3],
                            bf[j][0], bf[j][1]);
        }
        __syncthreads();
    }

    if (MODE == 0) {
#pragma unroll
        for (int i = 0; i < 4; i++) {
            const int r0 = rowBase + wm * 64 + i * 16 + (lane >> 2);
#pragma unroll
            for (int j = 0; j < 8; j++) {
                const int c0 = colBase + wn * 64 + j * 8 + (lane & 3) * 2;
                float bx = bias[c0], by = bias[c0 + 1];
                float2 v0 = { acc[i][j][0] + bx, acc[i][j][1] + by };
                float2 v1 = { acc[i][j][2] + bx, acc[i][j][3] + by };
                *(float2*)&Y[(size_t)r0 * EMB + c0]       = v0;
                *(float2*)&Y[(size_t)(r0 + 8) * EMB + c0] = v1;
            }
        }
    } else {
        const int mat = blockIdx.x >> 2;       // 0=Q, 1=K, 2=V
        __half* dst = (mat == 0) ? Qp : (mat == 1) ? Kp : Vp;
        const float scale = (mat == 0) ? qscale : 1.0f;
        const int colLoc = (colBase & 1023);
#pragma unroll
        for (int i = 0; i < 4; i++) {
            const int r0 = rowBase + wm * 64 + i * 16 + (lane >> 2);
#pragma unroll
            for (int j = 0; j < 8; j++) {
                const int c0 = colLoc + wn * 64 + j * 8 + (lane & 3) * 2;
#pragma unroll
                for (int rr = 0; rr < 2; rr++) {
                    __half2 v = __floats2half2_rn(acc[i][j][rr*2 + 0] * scale,
                                                  acc[i][j][rr*2 + 1] * scale);
                    *reinterpret_cast<__half2*>(&dst[(size_t)(r0 + rr*8) * EMB + c0]) = v;
                }
            }
        }
    }
}

// ---------------------------------------------------------------------------
// fp16 tensor-core causal flash attention (exactly round 13 — best config).
// P = exp2(s) raw via ex2.approx.f16x2; l via tensor-core ones-MMA.
// CTA: 64 q rows, 128 threads (4 warps). Bc=64 tiles, double-buffered KV.
// Diagonal tile peeled with per-warp causal culling.
// ---------------------------------------------------------------------------
#define AROWB   144
#define QT      (64 * AROWB)             // 9216
#define KVT     (64 * AROWB)             // 9216
#define KVST    (2 * KVT)
#define ATTN_SMEM (QT + 2*KVST)          // 46080

__global__ __launch_bounds__(128, 4)
void attn_mma(const __half* __restrict__ Qg,
              const __half* __restrict__ Kg, const __half* __restrict__ Vg,
              __half* __restrict__ C)
{
    extern __shared__ char sm[];
    const uint32_t smb = smem_u32(sm);
    const int tid  = threadIdx.x;
    const int lane = tid & 31;
    const int wid  = tid >> 5;
    const int qb = gridDim.x - 1 - blockIdx.x;      // heavy CTAs first
    const int h = blockIdx.y, b = blockIdx.z;
    const size_t tok0 = (size_t)b * SEQ;
    const int col0  = h * HD;
    const int qrow0 = qb * 64;

#pragma unroll
    for (int i = 0; i < 4; i++) {
        int idx = tid + i * 128;
        int row = idx >> 3, seg = idx & 7;
        const __half* src = Qg + (tok0 + qrow0 + row) * EMB + col0 + seg * 8;
        CP_ASYNC16(smb + (uint32_t)row * AROWB + seg * 16, src);
    }
    CP_COMMIT();

    auto load_kv = [&](int t) {
        const int st = t & 1;
        const int kt = t * 64;
        const uint32_t sb = smb + QT + st * KVST;
#pragma unroll
        for (int i = 0; i < 8; i++) {
            int idx  = tid + i * 128;
            int arr  = idx >> 9;
            int idx2 = idx & 511;
            int row  = idx2 >> 3, seg = idx2 & 7;
            const __half* src =
                (arr ? Vg : Kg) + (tok0 + kt + row) * EMB + col0 + seg * 8;
            CP_ASYNC16(sb + arr * KVT + (uint32_t)row * AROWB + seg * 16, src);
        }
        CP_COMMIT();
    };
    load_kv(0);

    const int aRow = (lane & 7) + ((lane >> 3) & 1) * 8;
    const int aK   = (lane >> 4) * 8;
    const int kRow = (lane & 7) + (lane >> 4) * 8;
    const int kC   = ((lane >> 3) & 1) * 8;

    uint32_t qf[4][4];
    CP_WAIT1();
    __syncthreads();
#pragma unroll
    for (int k16 = 0; k16 < 4; k16++) {
        const uint32_t qoff = (uint32_t)(wid*16 + aRow) * AROWB + (k16*16 + aK) * 2;
        LDMATRIX_X4(qf[k16][0], qf[k16][1], qf[k16][2], qf[k16][3], smb + qoff);
    }

    float cl[4];
#pragma unroll
    for (int r = 0; r < 4; r++) cl[r] = 0.f;
    float ctx[8][4];
#pragma unroll
    for (int j = 0; j < 8; j++)
#pragma unroll
        for (int r = 0; r < 4; r++) ctx[j][r] = 0.f;

    const int ntiles = qb + 1;

    // ---- main loop: full tiles, no causal mask ----
    for (int t = 0; t < ntiles - 1; t++) {
        load_kv(t + 1);
        CP_WAIT1();
        __syncthreads();

        const uint32_t sb = smb + QT + (t & 1) * KVST;

        float s[8][4];
#pragma unroll
        for (int j = 0; j < 8; j++)
#pragma unroll
            for (int r = 0; r < 4; r++) s[j][r] = 0.f;

#pragma unroll
        for (int k16 = 0; k16 < 4; k16++) {
            uint32_t kf[4][4];
#pragma unroll
            for (int pr = 0; pr < 4; pr++) {
                const uint32_t koff = (uint32_t)(pr*16 + kRow) * AROWB + (k16*16 + kC) * 2;
                LDMATRIX_X4(kf[pr][0], kf[pr][1], kf[pr][2], kf[pr][3], sb + koff);
            }
#pragma unroll
            for (int j = 0; j < 8; j++) {
                const uint32_t b0 = kf[j>>1][(j&1)*2], b1 = kf[j>>1][(j&1)*2 + 1];
                MMA_F16(s[j][0], s[j][1], s[j][2], s[j][3],
                        qf[k16][0], qf[k16][1], qf[k16][2], qf[k16][3], b0, b1);
            }
        }

#pragma unroll
        for (int k16 = 0; k16 < 4; k16++) {
            uint32_t aH[4];
#pragma unroll
            for (int g = 0; g < 2; g++) {
                const int j = 2*k16 + g;
                uint32_t p01 = pack_h2(s[j][0], s[j][1]);
                uint32_t p23 = pack_h2(s[j][2], s[j][3]);
                EX2_H2(p01);
                EX2_H2(p23);
                aH[2*g + 0] = p01;
                aH[2*g + 1] = p23;
            }

            uint32_t vf[4][4];
#pragma unroll
            for (int dp = 0; dp < 4; dp++) {
                const uint32_t voff = (uint32_t)(k16*16 + aRow) * AROWB + (dp*16 + aK) * 2;
                LDMATRIX_X4_T(vf[dp][0], vf[dp][1], vf[dp][2], vf[dp][3],
                              sb + KVT + voff);
            }
#pragma unroll
            for (int j = 0; j < 8; j++) {
                const uint32_t b0 = vf[j>>1][(j&1)*2], b1 = vf[j>>1][(j&1)*2 + 1];
                MMA_F16(ctx[j][0], ctx[j][1], ctx[j][2], ctx[j][3],
                        aH[0], aH[1], aH[2], aH[3], b0, b1);
            }
            MMA_F16(cl[0], cl[1], cl[2], cl[3],
                    aH[0], aH[1], aH[2], aH[3], HONES, HONES);
        }
        __syncthreads();
    }

    // ---- peeled diagonal tile: per-warp causal culling ----
    {
        CP_WAIT0();
        __syncthreads();

        const uint32_t sb = smb + QT + ((ntiles - 1) & 1) * KVST;
        const int kt = (ntiles - 1) * 64;
        const int r0g = qrow0 + wid*16 + (lane >> 2);
        const int jmax = 2*wid + 2;

        float s[8][4];
#pragma unroll
        for (int j = 0; j < 8; j++)
#pragma unroll
            for (int r = 0; r < 4; r++) s[j][r] = 0.f;

#pragma unroll
        for (int k16 = 0; k16 < 4; k16++) {
            uint32_t kf[4][4];
#pragma unroll
            for (int pr = 0; pr < 4; pr++) {
                if (pr <= wid) {
                    const uint32_t koff = (uint32_t)(pr*16 + kRow) * AROWB + (k16*16 + kC) * 2;
                    LDMATRIX_X4(kf[pr][0], kf[pr][1], kf[pr][2], kf[pr][3], sb + koff);
                }
            }
#pragma unroll
            for (int j = 0; j < 8; j++) {
                if (j < jmax) {
                    const uint32_t b0 = kf[j>>1][(j&1)*2], b1 = kf[j>>1][(j&1)*2 + 1];
                    MMA_F16(s[j][0], s[j][1], s[j][2], s[j][3],
                            qf[k16][0], qf[k16][1], qf[k16][2], qf[k16][3], b0, b1);
                }
            }
        }

#pragma unroll
        for (int j = 0; j < 8; j++) {
            if (j < jmax) {
                const int c = kt + j*8 + (lane & 3)*2;
                if (c     > r0g)     s[j][0] = -1e30f;
                if (c + 1 > r0g)     s[j][1] = -1e30f;
                if (c     > r0g + 8) s[j][2] = -1e30f;
                if (c + 1 > r0g + 8) s[j][3] = -1e30f;
            }
        }

#pragma unroll
        for (int k16 = 0; k16 < 4; k16++) {
            if (k16 <= wid) {
                uint32_t aH[4];
#pragma unroll
                for (int g = 0; g < 2; g++) {
                    const int j = 2*k16 + g;
                    uint32_t p01 = pack_h2(s[j][0], s[j][1]);
                    uint32_t p23 = pack_h2(s[j][2], s[j][3]);
                    EX2_H2(p01);
                    EX2_H2(p23);
                    aH[2*g + 0] = p01;
                    aH[2*g + 1] = p23;
                }

                uint32_t vf[4][4];
#pragma unroll
                for (int dp = 0; dp < 4; dp++) {
                    const uint32_t voff = (uint32_t)(k16*16 + aRow) * AROWB + (dp*16 + aK) * 2;
                    LDMATRIX_X4_T(vf[dp][0], vf[dp][1], vf[dp][2], vf[dp][3],
                                  sb + KVT + voff);
                }
#pragma unroll
                for (int j = 0; j < 8; j++) {
                    const uint32_t b0 = vf[j>>1][(j&1)*2], b1 = vf[j>>1][(j&1)*2 + 1];
                    MMA_F16(ctx[j][0], ctx[j][1], ctx[j][2], ctx[j][3],
                            aH[0], aH[1], aH[2], aH[3], b0, b1);
                }
                MMA_F16(cl[0], cl[1], cl[2], cl[3],
                        aH[0], aH[1], aH[2], aH[3], HONES, HONES);
            }
        }
    }

    const float inv0 = 1.f / cl[0], inv1 = 1.f / cl[2];

    const size_t rt0 = tok0 + qrow0 + wid*16 + (lane >> 2);
#pragma unroll
    for (int j = 0; j < 8; j++) {
        const int c = col0 + j*8 + (lane & 3)*2;
#pragma unroll
        for (int rr = 0; rr < 2; rr++) {
            __half2 v = __floats2half2_rn(ctx[j][rr*2 + 0] * (rr ? inv1 : inv0),
                                          ctx[j][rr*2 + 1] * (rr ? inv1 : inv0));
            *reinterpret_cast<__half2*>(&C[(rt0 + rr*8) * EMB + c]) = v;
        }
    }
}

// ---------------------------------------------------------------------------

extern "C" void kernel_launch(void* const* d_in, const int* in_sizes, int n_in,
                              void* d_out, int out_size)
{
    const float* x  = (const float*)d_in[0];
    const float* Wk = (const float*)d_in[1];
    const float* Wq = (const float*)d_in[2];
    const float* Wv = (const float*)d_in[3];
    const float* Wu = (const float*)d_in[4];
    const float* bu = (const float*)d_in[5];
    float* out = (float*)d_out;

    __half *Xp, *W, *Qp, *Kp, *Vp, *Cp;
    cudaGetSymbolAddress((void**)&Xp, g_X);
    cudaGetSymbolAddress((void**)&W,  g_W);
    cudaGetSymbolAddress((void**)&Qp, g_Q);
    cudaGetSymbolAddress((void**)&Kp, g_K);
    cudaGetSymbolAddress((void**)&Vp, g_V);
    cudaGetSymbolAddress((void**)&Cp, g_C);

    cudaFuncSetAttribute((const void*)gemm_hmma<0>,
                         cudaFuncAttributeMaxDynamicSharedMemorySize, GEMM_SMEM);
    cudaFuncSetAttribute((const void*)gemm_hmma<1>,
                         cudaFuncAttributeMaxDynamicSharedMemorySize, GEMM_SMEM);
    cudaFuncSetAttribute((const void*)attn_mma,
                         cudaFuncAttributeMaxDynamicSharedMemorySize, ATTN_SMEM);

    const float QSCALE = 0.125f * 1.44269504088896340736f;

    {
        dim3 pgrid(512, 8);
        prep_kernel<<<pgrid, 256>>>(x, Wq, Wk, Wv, Wu, W, Xp);
    }

    // fused Q/K/V projection: B rows 0..3071 = (Wq|Wk|Wv)
    {
        dim3 g(12, 32);                       // 384 CTAs, 128x256 tiles, BK=64
        gemm_hmma<1><<<g, 256, GEMM_SMEM>>>(Xp, W, nullptr, nullptr,
                                            Qp, Kp, Vp, QSCALE, EMB);
    }

    {
        dim3 agrid(SEQ / 64, NH, BATCH);      // 1024 CTAs (round-13 attention)
        attn_mma<<<agrid, 128, ATTN_SMEM>>>(Qp, Kp, Vp, Cp);
    }

    {
        dim3 g(4, 32);                        // 128 CTAs, 128x256 tiles, BK=64
        gemm_hmma<0><<<g, 256, GEMM_SMEM>>>(Cp, W + 3ll*EMB*EMB, out, bu,
                                            nullptr, nullptr, nullptr, 1.0f, EMB);
    }
}